// round 8
// baseline (speedup 1.0000x reference)
#include <cuda_runtime.h>
#include <cuda.h>
#include <cstdint>

#define NQ 4096
#define TPB 256

// SW128 word-level swizzle (matches CU_TENSOR_MAP_SWIZZLE_128B for 4B elems):
// XOR word bits 5..7 (= 128B-row index mod 8) into bits 2..4 (16B-chunk index).
// Bank bits of s(w): {w0, w1, w2^w5, w3^w6, w4^w7}. 16B alignment preserved.
__device__ __forceinline__ int swz(int w) {
    return w ^ (((w >> 5) & 7) << 2);
}

__device__ __forceinline__ void butterfly16(float v[16]) {
#pragma unroll
    for (int bs = 1; bs < 16; bs <<= 1) {
#pragma unroll
        for (int i = 0; i < 16; i++) {
            if ((i & bs) == 0) {
                float a = v[i], b = v[i + bs];
                v[i] = a + b;
                v[i + bs] = a - b;
            }
        }
    }
}

// ---------------- TMA path ----------------
// 4096-pt FWHT. TMA(SW128) load -> 3 register phases over dim sets
// P1={7,9,10,11}, P2={4,5,6,8}, P3={0,1,2,3} with in-place SMEM exchanges
// (all patterns conflict-free under the SW128 swizzle) -> TMA store.
__global__ void __launch_bounds__(TPB, 8) fwht4096_tma_kernel(
    const __grid_constant__ CUtensorMap tmap_in,
    const __grid_constant__ CUtensorMap tmap_out) {
    __shared__ alignas(1024) float sm[NQ];  // 16 KB tile, SW128 layout
    __shared__ alignas(8) uint64_t mbar;

    const int t = threadIdx.x;
    const int row0 = blockIdx.x * 128;  // 128 x 32-float rows per FWHT row
    float v[16];

    uint32_t mb;
    asm("{ .reg .u64 a; cvta.to.shared.u64 a, %1; cvt.u32.u64 %0, a; }"
        : "=r"(mb) : "l"(&mbar));
    uint32_t smaddr;
    asm("{ .reg .u64 a; cvta.to.shared.u64 a, %1; cvt.u32.u64 %0, a; }"
        : "=r"(smaddr) : "l"(sm));

    // ---- mbarrier init, THEN barrier, THEN TMA issue (fixes R7 race) ----
    if (t == 0) {
        asm volatile("mbarrier.init.shared.b64 [%0], 1;" :: "r"(mb) : "memory");
        asm volatile("fence.proxy.async.shared::cta;" ::: "memory");
    }
    __syncthreads();  // all threads must see an initialized mbarrier

    if (t == 0) {
        asm volatile("mbarrier.arrive.expect_tx.shared.b64 _, [%0], %1;"
                     :: "r"(mb), "r"(NQ * 4) : "memory");
        asm volatile(
            "cp.async.bulk.tensor.2d.shared::cta.global.tile.mbarrier::complete_tx::bytes "
            "[%0], [%1, {%2, %3}], [%4];"
            :: "r"(smaddr), "l"(&tmap_in), "r"(0), "r"(row0), "r"(mb)
            : "memory");
    }
    // Wait for TMA completion (phase 0)
    asm volatile(
        "{\n\t.reg .pred P;\n"
        "W_%=:\n\t"
        "mbarrier.try_wait.parity.shared::cta.b64 P, [%0], 0;\n\t"
        "@!P bra W_%=;\n\t}"
        :: "r"(mb) : "memory");

    // ---- Phase 1: dims {7,9,10,11} in regs ----
    // Thread owns dims 0-6 (t0-6) and dim 8 (t7). Lane-contiguous reads: CF.
    const float scale = 0.015625f;  // 1/sqrt(4096)
    const int eb0 = (t & 127) | (((t >> 7) & 1) << 8);
#pragma unroll
    for (int r = 0; r < 16; r++) {
        int e = eb0 | ((r & 1) << 7) | ((r >> 1) << 9);
        v[r] = sm[swz(e)] * scale;
    }
    butterfly16(v);
#pragma unroll
    for (int r = 0; r < 16; r++) {  // write back to own addresses
        int e = eb0 | ((r & 1) << 7) | ((r >> 1) << 9);
        sm[swz(e)] = v[r];
    }
    __syncthreads();

    // ---- Phase 2: dims {4,5,6,8} in regs ----
    // Thread owns dims 0-3 (t0-3), dim 7 (t4), dims 9-11 (t5-7).
    // Banks {lane0, lane1, lane2^c, lane3^c, lane4^c}: bijective -> CF.
    const int eb1 = (t & 15) | (((t >> 4) & 1) << 7) | ((t >> 5) << 9);
#pragma unroll
    for (int i = 0; i < 16; i++) {
        int e = eb1 | ((i & 7) << 4) | ((i >> 3) << 8);
        v[i] = sm[swz(e)];
    }
    butterfly16(v);
#pragma unroll
    for (int i = 0; i < 16; i++) {
        int e = eb1 | ((i & 7) << 4) | ((i >> 3) << 8);
        sm[swz(e)] = v[i];
    }
    __syncthreads();

    // ---- Phase 3: dims {0,1,2,3} in regs ----
    // float4 at w = 16t+4q: chunk index (q0^t1, q1^t2, t0^t3) -> 8 distinct
    // chunks per 8-lane phase: CF (SW128 design case).
#pragma unroll
    for (int q = 0; q < 4; q++) {
        int w = swz((t << 4) | (q << 2));
        float4 f = *reinterpret_cast<const float4*>(sm + w);
        v[4 * q + 0] = f.x;
        v[4 * q + 1] = f.y;
        v[4 * q + 2] = f.z;
        v[4 * q + 3] = f.w;
    }
    butterfly16(v);
#pragma unroll
    for (int q = 0; q < 4; q++) {
        int w = swz((t << 4) | (q << 2));
        *reinterpret_cast<float4*>(sm + w) =
            make_float4(v[4 * q], v[4 * q + 1], v[4 * q + 2], v[4 * q + 3]);
    }
    __syncthreads();

    // ---- TMA store: SMEM (SW128) -> global, de-swizzled ----
    if (t == 0) {
        asm volatile("fence.proxy.async.shared::cta;" ::: "memory");
        asm volatile(
            "cp.async.bulk.tensor.2d.global.shared::cta.tile.bulk_group "
            "[%0, {%1, %2}], [%3];"
            :: "l"(&tmap_out), "r"(0), "r"(row0), "r"(smaddr)
            : "memory");
        asm volatile("cp.async.bulk.commit_group;" ::: "memory");
        asm volatile("cp.async.bulk.wait_group 0;" ::: "memory");
    }
}

// ---------------- Fallback path (proven 45.8us radix-16^3 LDG kernel) ----------------
__device__ __forceinline__ int sidx(int e) {
    return e ^ (((e >> 5) & 3) << 2) ^ (((e >> 8) & 1) << 4);
}

__global__ void __launch_bounds__(TPB) fwht4096_ldg_kernel(const float* __restrict__ x,
                                                           float* __restrict__ y) {
    __shared__ float sm[NQ];
    const int t = threadIdx.x;
    const size_t base = (size_t)blockIdx.x * NQ;
    const float scale = 0.015625f;
    float v[16];
    {
        const float4* p = reinterpret_cast<const float4*>(x + base + 16 * t);
#pragma unroll
        for (int q = 0; q < 4; q++) {
            float4 f = p[q];
            v[4 * q + 0] = f.x * scale;
            v[4 * q + 1] = f.y * scale;
            v[4 * q + 2] = f.z * scale;
            v[4 * q + 3] = f.w * scale;
        }
    }
    butterfly16(v);
#pragma unroll
    for (int q = 0; q < 4; q++) {
        int sb = sidx(16 * t + 4 * q);
        *reinterpret_cast<float4*>(sm + sb) =
            make_float4(v[4 * q], v[4 * q + 1], v[4 * q + 2], v[4 * q + 3]);
    }
    __syncthreads();
    const int hi = (t >> 4) << 8;
    const int lo = t & 15;
#pragma unroll
    for (int i = 0; i < 16; i++) v[i] = sm[sidx(hi + i * 16 + lo)];
    butterfly16(v);
#pragma unroll
    for (int i = 0; i < 16; i++) sm[sidx(hi + i * 16 + lo)] = v[i];
    __syncthreads();
#pragma unroll
    for (int r = 0; r < 16; r++) v[r] = sm[sidx(r * 256 + t)];
    butterfly16(v);
    float* yr = y + base;
#pragma unroll
    for (int r = 0; r < 16; r++) yr[r * 256 + t] = v[r];
}

// ---- Host: build tensormaps via cudart driver-entry-point (no -lcuda) ----
typedef CUresult (*PFN_encodeTiled)(
    CUtensorMap*, CUtensorMapDataType, cuuint32_t, void*, const cuuint64_t*,
    const cuuint64_t*, const cuuint32_t*, const cuuint32_t*,
    CUtensorMapInterleave, CUtensorMapSwizzle, CUtensorMapL2promotion,
    CUtensorMapFloatOOBfill);

static PFN_encodeTiled get_encode_fn() {
    void* fn = nullptr;
    cudaDriverEntryPointQueryResult qr = cudaDriverEntryPointSymbolNotFound;
#if CUDART_VERSION >= 12050
    cudaGetDriverEntryPointByVersion("cuTensorMapEncodeTiled", &fn, 12000,
                                     cudaEnableDefault, &qr);
#else
    cudaGetDriverEntryPoint("cuTensorMapEncodeTiled", &fn, cudaEnableDefault, &qr);
#endif
    if (qr != cudaDriverEntryPointSuccess) return nullptr;
    return (PFN_encodeTiled)fn;
}

static bool make_tmap(CUtensorMap* tm, void* ptr, uint64_t n_rows32,
                      PFN_encodeTiled enc) {
    // 2D view: [32 floats (128B), n_rows32 rows]; box [32, 128] = one 16KB tile.
    cuuint64_t dims[2] = {32, n_rows32};
    cuuint64_t strides[1] = {128};  // bytes per row
    cuuint32_t box[2] = {32, 128};
    cuuint32_t estr[2] = {1, 1};
    CUresult r = enc(tm, CU_TENSOR_MAP_DATA_TYPE_FLOAT32, 2, ptr, dims, strides,
                     box, estr, CU_TENSOR_MAP_INTERLEAVE_NONE,
                     CU_TENSOR_MAP_SWIZZLE_128B, CU_TENSOR_MAP_L2_PROMOTION_L2_128B,
                     CU_TENSOR_MAP_FLOAT_OOB_FILL_NONE);
    return r == CUDA_SUCCESS;
}

extern "C" void kernel_launch(void* const* d_in, const int* in_sizes, int n_in,
                              void* d_out, int out_size) {
    const int rows = in_sizes[0] / NQ;           // 8192 FWHT rows
    const uint64_t n32 = (uint64_t)rows * 128;   // 128B-rows in the 2D view

    PFN_encodeTiled enc = get_encode_fn();
    CUtensorMap tin, tout;
    if (enc && make_tmap(&tin, (void*)d_in[0], n32, enc) &&
        make_tmap(&tout, d_out, n32, enc)) {
        fwht4096_tma_kernel<<<rows, TPB>>>(tin, tout);
    } else {
        fwht4096_ldg_kernel<<<rows, TPB>>>((const float*)d_in[0], (float*)d_out);
    }
}

// round 9
// speedup vs baseline: 1.0225x; 1.0225x over previous
#include <cuda_runtime.h>
#include <cstdint>

#define NQ 4096
#define TPB 256

// Swizzle: s(e) = e ^ ((e>>5 & 7)<<2) ^ ((e>>8 & 1)<<4).
// Bank bits of s(e): {e0, e1, e2^e5, e3^e6, e4^e7^e8}.
// Bijective on [0,4096); XORs only into bits 2-4 -> float4 alignment kept.
// Conflict-free for all three smem patterns used below (see analysis).
__device__ __forceinline__ int s_idx(int e) {
    return e ^ (((e >> 5) & 7) << 2) ^ (((e >> 8) & 1) << 4);
}

__device__ __forceinline__ void butterfly16(float v[16]) {
#pragma unroll
    for (int bs = 1; bs < 16; bs <<= 1) {
#pragma unroll
        for (int i = 0; i < 16; i++) {
            if ((i & bs) == 0) {
                float a = v[i], b = v[i + bs];
                v[i] = a + b;
                v[i + bs] = a - b;
            }
        }
    }
}

// 4096-pt FWHT, one row per CTA, 16 floats per thread.
//   P1: regs = dims {8,9,10,11}, loaded DIRECTLY from gmem (coalesced LDG.32)
//   P2: regs = dims {0,1,2,3}, via smem float4 (in-place exchange)
//   P3: regs = dims {4,5,6,7}, stored DIRECTLY to gmem (coalesced STG.32)
// Only ONE smem exchange pair (4 x 16KB smem legs total = 64KB/CTA).
__global__ void __launch_bounds__(TPB, 8) fwht4096_kernel(const float* __restrict__ x,
                                                          float* __restrict__ y) {
    __shared__ float sm[NQ];  // 16 KB
    const int t = threadIdx.x;
    const size_t base = (size_t)blockIdx.x * NQ;
    const float scale = 0.015625f;  // 1/sqrt(4096)
    float v[16];

    // ---- P1: v[r] = x[r*256 + t]; 16 coalesced LDG.32, huge MLP ----
    const float* xr = x + base + t;
#pragma unroll
    for (int r = 0; r < 16; r++)
        v[r] = xr[r * 256] * scale;
    butterfly16(v);  // dims 8-11

    // STS pattern A: e = r*256 + t (lanes vary e0-4 -> conflict-free)
#pragma unroll
    for (int r = 0; r < 16; r++)
        sm[s_idx(r * 256 + t)] = v[r];
    __syncthreads();

    // ---- P2: regs = dims 0-3; thread owns dims 4-11 (= t) ----
    // float4 at e = 16t + 4q: chunk bits {q0^t1, q1^t2, t0^t3} -> CF.
#pragma unroll
    for (int q = 0; q < 4; q++) {
        float4 f = *reinterpret_cast<const float4*>(sm + s_idx((t << 4) | (q << 2)));
        v[4 * q + 0] = f.x;
        v[4 * q + 1] = f.y;
        v[4 * q + 2] = f.z;
        v[4 * q + 3] = f.w;
    }
    butterfly16(v);  // dims 0-3
    // In-place write-back to the same addresses (thread-private set)
#pragma unroll
    for (int q = 0; q < 4; q++) {
        *reinterpret_cast<float4*>(sm + s_idx((t << 4) | (q << 2))) =
            make_float4(v[4 * q], v[4 * q + 1], v[4 * q + 2], v[4 * q + 3]);
    }
    __syncthreads();

    // ---- P3: regs = dims 4-7; thread owns dims 0-3 (t&15) + 8-11 (t>>4) ----
    // LDS pattern C: e = (t&15) | (i<<4) | ((t>>4)<<8)
    // banks {t0, t1, t2^i1, t3^i2, i0^i3^t4} -> bijective over lanes: CF.
    const int ebase = (t & 15) | ((t >> 4) << 8);
#pragma unroll
    for (int i = 0; i < 16; i++)
        v[i] = sm[s_idx(ebase | (i << 4))];
    butterfly16(v);  // dims 4-7

    // ---- Store: 16 STG.32; per instruction lanes cover two full 64B segments ----
    float* yr = y + base;
#pragma unroll
    for (int i = 0; i < 16; i++)
        yr[ebase | (i << 4)] = v[i];
}

extern "C" void kernel_launch(void* const* d_in, const int* in_sizes, int n_in,
                              void* d_out, int out_size) {
    const float* x = (const float*)d_in[0];
    float* y = (float*)d_out;
    const int rows = in_sizes[0] / NQ;  // 8192 rows
    fwht4096_kernel<<<rows, TPB>>>(x, y);
}